// round 1
// baseline (speedup 1.0000x reference)
#include <cuda_runtime.h>
#include <cstddef>

// Problem constants
#define B_   64
#define S_   256
#define H_   512
#define E_   256
#define V_   32000
#define ML_  32256
#define D2H  1024          // 2*H
#define XW   1536          // 3*H (width of x, gi, gh)
#define X1W  1280          // 2*H + E

// ---------------- scratch (device globals; no allocation allowed) ----------------
__device__ float g_attn_strength[B_ * D2H];
__device__ float g_scores[B_ * S_];          // attn scores -> weights (in place)
__device__ float g_x1[B_ * X1W];             // [context | embedding]
__device__ float g_x [B_ * XW];              // [attn_reading | select_reading]
__device__ float g_gi[B_ * XW];
__device__ float g_gh[B_ * XW];
__device__ float g_state[B_ * H_];
__device__ float g_logits[B_ * ML_];         // [score_g | score_c] -> probs (in place)
__device__ float g_part[8 * B_ * XW];        // split-K partials (reused per GEMM)
__device__ float g_scpart[4 * B_ * S_];      // score_c N-tile partials

// ---------------- generic fp32 GEMM: C[64,N] = A[64,K] @ B[N,K]^T (+bias) --------
// BM=64, BN=128, BK=16, 256 threads, 4x8 microtile per thread.
// kSplit>1: writes per-split partials to g_part (reduced later, fixed order).
__global__ void __launch_bounds__(256) gemm64_kernel(
    const float* __restrict__ A, int lda,
    const float* __restrict__ Bm,
    const float* __restrict__ bias,
    float* __restrict__ C, int ldc,
    int N, int K, int kSplit)
{
    __shared__ float As[16][64];
    __shared__ float Bs[16][128];
    const int tid  = threadIdx.x;
    const int tx   = tid & 15;
    const int ty   = tid >> 4;
    const int arow = tid >> 2;           // 0..63
    const int akv  = (tid & 3) * 4;      // 0,4,8,12
    const int n0   = blockIdx.x * 128;
    const int kLen = K / kSplit;
    const int k0   = blockIdx.y * kLen;

    const float* Ag  = A  + (size_t)arow * lda + k0 + akv;
    const float* Bg0 = Bm + (size_t)(n0 + arow) * K + k0 + akv;
    const float* Bg1 = Bm + (size_t)(n0 + 64 + arow) * K + k0 + akv;

    float acc[4][8];
    #pragma unroll
    for (int i = 0; i < 4; i++)
        #pragma unroll
        for (int j = 0; j < 8; j++) acc[i][j] = 0.f;

    for (int kb = 0; kb < kLen; kb += 16) {
        float4 av  = *(const float4*)(Ag  + kb);
        float4 bv0 = *(const float4*)(Bg0 + kb);
        float4 bv1 = *(const float4*)(Bg1 + kb);
        __syncthreads();
        As[akv+0][arow] = av.x;  As[akv+1][arow] = av.y;
        As[akv+2][arow] = av.z;  As[akv+3][arow] = av.w;
        Bs[akv+0][arow] = bv0.x; Bs[akv+1][arow] = bv0.y;
        Bs[akv+2][arow] = bv0.z; Bs[akv+3][arow] = bv0.w;
        Bs[akv+0][64+arow] = bv1.x; Bs[akv+1][64+arow] = bv1.y;
        Bs[akv+2][64+arow] = bv1.z; Bs[akv+3][64+arow] = bv1.w;
        __syncthreads();
        #pragma unroll
        for (int k = 0; k < 16; k++) {
            float4 a  = *(const float4*)&As[k][ty*4];
            float4 b0 = *(const float4*)&Bs[k][tx*8];
            float4 b1 = *(const float4*)&Bs[k][tx*8+4];
            float ar[4] = {a.x, a.y, a.z, a.w};
            float br[8] = {b0.x, b0.y, b0.z, b0.w, b1.x, b1.y, b1.z, b1.w};
            #pragma unroll
            for (int i = 0; i < 4; i++)
                #pragma unroll
                for (int j = 0; j < 8; j++)
                    acc[i][j] = fmaf(ar[i], br[j], acc[i][j]);
        }
    }

    if (kSplit == 1) {
        #pragma unroll
        for (int i = 0; i < 4; i++) {
            int r = ty*4 + i;
            #pragma unroll
            for (int j = 0; j < 8; j++) {
                int c = n0 + tx*8 + j;
                float v = acc[i][j];
                if (bias) v += bias[c];
                C[(size_t)r * ldc + c] = v;
            }
        }
    } else {
        float* P = g_part + (size_t)blockIdx.y * 64 * N;
        #pragma unroll
        for (int i = 0; i < 4; i++) {
            int r = ty*4 + i;
            #pragma unroll
            for (int j = 0; j < 8; j++) {
                int c = n0 + tx*8 + j;
                P[(size_t)r * N + c] = acc[i][j];
            }
        }
    }
}

// Fixed-order (deterministic) split-K reduction: C = bias + sum_z part[z]
__global__ void splitk_reduce(const float* __restrict__ bias,
                              float* __restrict__ C, int ldc, int N, int kSplit)
{
    int idx = blockIdx.x * blockDim.x + threadIdx.x;
    int total = 64 * N;
    if (idx >= total) return;
    int m = idx / N, n = idx - m * N;
    float s = bias ? bias[n] : 0.f;
    for (int z = 0; z < kSplit; z++) s += g_part[(size_t)z * total + idx];
    C[(size_t)m * ldc + n] = s;
}

// ---------------- score_c fused kernel -------------------------------------------
// For batch b, s-tile (64 rows), h-tile (128 cols):
//   F = enc_tile @ W_c^T ; partial[s] = sum_h tanh(F + b_c[h]) * state[b,h]
// Writes per-h-tile partials to g_scpart (reduced in fixed order by scred_kernel).
__global__ void __launch_bounds__(256) score_c_kernel(
    const float* __restrict__ enc,
    const float* __restrict__ W_c,
    const float* __restrict__ b_c,
    const float* __restrict__ state)
{
    __shared__ float As[16][64];
    __shared__ float Bs[16][128];
    __shared__ float red[64][17];
    const int tid  = threadIdx.x;
    const int tx   = tid & 15;
    const int ty   = tid >> 4;
    const int arow = tid >> 2;
    const int akv  = (tid & 3) * 4;
    const int s0   = blockIdx.x * 64;       // 0..3
    const int n0   = blockIdx.y * 128;      // 0..3
    const int b    = blockIdx.z;
    const int K    = D2H;                   // 1024

    const float* A   = enc + ((size_t)b * S_ + s0) * K;
    const float* Ag  = A   + (size_t)arow * K + akv;
    const float* Bg0 = W_c + (size_t)(n0 + arow) * K + akv;
    const float* Bg1 = W_c + (size_t)(n0 + 64 + arow) * K + akv;

    float acc[4][8];
    #pragma unroll
    for (int i = 0; i < 4; i++)
        #pragma unroll
        for (int j = 0; j < 8; j++) acc[i][j] = 0.f;

    for (int kb = 0; kb < K; kb += 16) {
        float4 av  = *(const float4*)(Ag  + kb);
        float4 bv0 = *(const float4*)(Bg0 + kb);
        float4 bv1 = *(const float4*)(Bg1 + kb);
        __syncthreads();
        As[akv+0][arow] = av.x;  As[akv+1][arow] = av.y;
        As[akv+2][arow] = av.z;  As[akv+3][arow] = av.w;
        Bs[akv+0][arow] = bv0.x; Bs[akv+1][arow] = bv0.y;
        Bs[akv+2][arow] = bv0.z; Bs[akv+3][arow] = bv0.w;
        Bs[akv+0][64+arow] = bv1.x; Bs[akv+1][64+arow] = bv1.y;
        Bs[akv+2][64+arow] = bv1.z; Bs[akv+3][64+arow] = bv1.w;
        __syncthreads();
        #pragma unroll
        for (int k = 0; k < 16; k++) {
            float4 a  = *(const float4*)&As[k][ty*4];
            float4 b0 = *(const float4*)&Bs[k][tx*8];
            float4 b1 = *(const float4*)&Bs[k][tx*8+4];
            float ar[4] = {a.x, a.y, a.z, a.w};
            float br[8] = {b0.x, b0.y, b0.z, b0.w, b1.x, b1.y, b1.z, b1.w};
            #pragma unroll
            for (int i = 0; i < 4; i++)
                #pragma unroll
                for (int j = 0; j < 8; j++)
                    acc[i][j] = fmaf(ar[i], br[j], acc[i][j]);
        }
    }

    // epilogue: tanh + weighted reduction over h
    float st[8], bc[8];
    #pragma unroll
    for (int j = 0; j < 8; j++) {
        int c = n0 + tx*8 + j;
        st[j] = state[(size_t)b * H_ + c];
        bc[j] = b_c[c];
    }
    float part[4];
    #pragma unroll
    for (int i = 0; i < 4; i++) {
        float p = 0.f;
        #pragma unroll
        for (int j = 0; j < 8; j++)
            p += tanhf(acc[i][j] + bc[j]) * st[j];
        part[i] = p;
    }
    __syncthreads();
    #pragma unroll
    for (int i = 0; i < 4; i++) red[ty*4 + i][tx] = part[i];
    __syncthreads();
    if (tid < 64) {
        float s = 0.f;
        #pragma unroll
        for (int x = 0; x < 16; x++) s += red[tid][x];
        g_scpart[(size_t)blockIdx.y * (B_ * S_) + b * S_ + s0 + tid] = s;
    }
}

__global__ void scred_kernel()
{
    int idx = blockIdx.x * 256 + threadIdx.x;   // 64*256
    int b = idx >> 8, s = idx & 255;
    float v = g_scpart[idx] + g_scpart[B_*S_ + idx]
            + g_scpart[2*B_*S_ + idx] + g_scpart[3*B_*S_ + idx];
    g_logits[(size_t)b * ML_ + V_ + s] = v;
}

// ---------------- attention scores: scores[b,s] = enc[b,s,:] . strength[b,:] -----
__global__ void __launch_bounds__(256) attn_score_kernel(const float* __restrict__ enc)
{
    __shared__ float sm[D2H];
    const int b = blockIdx.x, t = threadIdx.x;
    for (int d = t; d < D2H; d += 256) sm[d] = g_attn_strength[b * D2H + d];
    __syncthreads();
    const int warp = t >> 5, lane = t & 31;
    #pragma unroll
    for (int r = 0; r < 4; r++) {
        int s = blockIdx.y * 32 + warp + r * 8;
        const float4* row = (const float4*)(enc + ((size_t)b * S_ + s) * D2H);
        float sum = 0.f;
        for (int q = lane; q < D2H/4; q += 32) {
            float4 v = row[q];
            sum += v.x*sm[q*4] + v.y*sm[q*4+1] + v.z*sm[q*4+2] + v.w*sm[q*4+3];
        }
        #pragma unroll
        for (int o = 16; o; o >>= 1) sum += __shfl_down_sync(0xffffffffu, sum, o);
        if (lane == 0) g_scores[b * S_ + s] = sum;
    }
}

__global__ void softmax256()
{
    int b = blockIdx.x, t = threadIdx.x;
    __shared__ float sm[256];
    float v = g_scores[b * S_ + t];
    sm[t] = v; __syncthreads();
    for (int o = 128; o; o >>= 1) { if (t < o) sm[t] = fmaxf(sm[t], sm[t+o]); __syncthreads(); }
    float m = sm[0]; __syncthreads();
    float e = expf(v - m);
    sm[t] = e; __syncthreads();
    for (int o = 128; o; o >>= 1) { if (t < o) sm[t] += sm[t+o]; __syncthreads(); }
    g_scores[b * S_ + t] = e / sm[0];
}

// ---------------- context + select_reading (one pass over enc) -------------------
__global__ void __launch_bounds__(256) ctxsel_kernel(
    const float* __restrict__ enc, const int* __restrict__ seq,
    const int* __restrict__ input_idx, const float* __restrict__ ppc)
{
    const int b = blockIdx.x;
    const int t = threadIdx.x;
    const int d = blockIdx.y * 256 + t;
    __shared__ float w[S_], sw[S_];
    int idxb = input_idx[b];
    w[t]  = g_scores[b * S_ + t];
    sw[t] = (seq[b * S_ + t] == idxb) ? ppc[b * S_ + t] : 0.f;
    __syncthreads();
    const float* e = enc + (size_t)b * S_ * D2H + d;
    float ctx = 0.f, sel = 0.f;
    #pragma unroll 4
    for (int s = 0; s < S_; s++) {
        float v = e[(size_t)s * D2H];
        ctx = fmaf(w[s], v, ctx);
        sel = fmaf(sw[s], v, sel);
    }
    g_x1[b * X1W + d]      = ctx;
    g_x [b * XW + H_ + d]  = sel;    // select_reading goes to cols [512,1536)
}

__global__ void embed_kernel(const int* __restrict__ input_idx,
                             const float* __restrict__ table)
{
    int b = blockIdx.x, t = threadIdx.x;
    int idx = input_idx[b];
    if (idx >= V_) idx = 2;
    g_x1[b * X1W + D2H + t] = table[(size_t)idx * E_ + t];
}

// ---------------- GRU cell --------------------------------------------------------
__global__ void gru_kernel(const float* __restrict__ pre_state, float* __restrict__ out_state)
{
    int b = blockIdx.x, h = threadIdx.x;   // 512 threads
    float ir = g_gi[b*XW + h],        hr = g_gh[b*XW + h];
    float iz = g_gi[b*XW + H_ + h],   hz = g_gh[b*XW + H_ + h];
    float in_= g_gi[b*XW + 2*H_ + h], hn = g_gh[b*XW + 2*H_ + h];
    float r = 1.f / (1.f + expf(-(ir + hr)));
    float z = 1.f / (1.f + expf(-(iz + hz)));
    float n = tanhf(in_ + r * hn);
    float ps = pre_state[b * H_ + h];
    float st = (1.f - z) * n + z * ps;
    g_state[b * H_ + h] = st;
    out_state[b * H_ + h] = st;
}

// ---------------- big softmax over 32256 ------------------------------------------
__global__ void __launch_bounds__(1024) softmax_big()
{
    int b = blockIdx.x, t = threadIdx.x;
    float* row = g_logits + (size_t)b * ML_;
    __shared__ float sred[32];
    float m = -1e30f;
    for (int i = t; i < ML_; i += 1024) m = fmaxf(m, row[i]);
    #pragma unroll
    for (int o = 16; o; o >>= 1) m = fmaxf(m, __shfl_xor_sync(0xffffffffu, m, o));
    if ((t & 31) == 0) sred[t >> 5] = m;
    __syncthreads();
    if (t < 32) {
        float x = sred[t];
        #pragma unroll
        for (int o = 16; o; o >>= 1) x = fmaxf(x, __shfl_xor_sync(0xffffffffu, x, o));
        sred[t] = x;
    }
    __syncthreads();
    m = sred[0];
    __syncthreads();
    float sum = 0.f;
    for (int i = t; i < ML_; i += 1024) {
        float e = expf(row[i] - m);
        row[i] = e;
        sum += e;
    }
    #pragma unroll
    for (int o = 16; o; o >>= 1) sum += __shfl_xor_sync(0xffffffffu, sum, o);
    if ((t & 31) == 0) sred[t >> 5] = sum;
    __syncthreads();
    if (t < 32) {
        float x = sred[t];
        #pragma unroll
        for (int o = 16; o; o >>= 1) x += __shfl_xor_sync(0xffffffffu, x, o);
        sred[t] = x;
    }
    __syncthreads();
    float inv = 1.f / sred[0];
    for (int i = t; i < ML_; i += 1024) row[i] *= inv;
}

// ---------------- final outputs ----------------------------------------------------
__global__ void outbase_kernel(float* __restrict__ out)
{
    int idx = blockIdx.x * 256 + threadIdx.x;   // 64*32256 total
    int v = idx % ML_;
    out[idx] = (v < V_) ? g_logits[idx] : 0.f;
}

__global__ void probc_kernel(const int* __restrict__ seq, float* __restrict__ out)
{
    int b = blockIdx.x, j = threadIdx.x;
    __shared__ int   sq[S_];
    __shared__ float pc[S_];
    sq[j] = seq[b * S_ + j];
    pc[j] = g_logits[(size_t)b * ML_ + V_ + j];
    __syncthreads();
    int tok = sq[j];
    float sum = 0.f;
    bool first = true;
    for (int i = 0; i < S_; i++) {
        bool mq = (sq[i] == tok);
        if (mq) sum += pc[i];
        if (mq && i < j) first = false;
    }
    // prob_c output (third output region)
    out[(size_t)B_ * ML_ + (size_t)B_ * H_ + b * S_ + j] = sum;
    // scatter: set on zero base, prob_g already added (unique writer per token per b)
    if (first) out[(size_t)b * ML_ + tok] += sum;
}

// ---------------- launch -----------------------------------------------------------
extern "C" void kernel_launch(void* const* d_in, const int* in_sizes, int n_in,
                              void* d_out, int out_size)
{
    const int*   input_idx = (const int*)  d_in[0];
    const float* enc       = (const float*)d_in[1];
    const int*   seq       = (const int*)  d_in[2];
    const float* pre_state = (const float*)d_in[3];
    const float* ppc       = (const float*)d_in[4];
    const float* table     = (const float*)d_in[5];
    const float* W_aw = (const float*)d_in[6];  const float* b_aw = (const float*)d_in[7];
    const float* W_ac = (const float*)d_in[8];  const float* b_ac = (const float*)d_in[9];
    const float* W_ih = (const float*)d_in[10]; const float* b_ih = (const float*)d_in[11];
    const float* W_hh = (const float*)d_in[12]; const float* b_hh = (const float*)d_in[13];
    const float* W_o  = (const float*)d_in[14]; const float* b_o  = (const float*)d_in[15];
    const float* W_c  = (const float*)d_in[16]; const float* b_c  = (const float*)d_in[17];
    float* out = (float*)d_out;

    float *attn_strength, *x1, *x, *gi, *gh, *state, *logits;
    cudaGetSymbolAddress((void**)&attn_strength, g_attn_strength);
    cudaGetSymbolAddress((void**)&x1, g_x1);
    cudaGetSymbolAddress((void**)&x,  g_x);
    cudaGetSymbolAddress((void**)&gi, g_gi);
    cudaGetSymbolAddress((void**)&gh, g_gh);
    cudaGetSymbolAddress((void**)&state,  g_state);
    cudaGetSymbolAddress((void**)&logits, g_logits);

    // 1) embedding gather -> g_x1[:,1024:1280]
    embed_kernel<<<B_, E_>>>(input_idx, table);

    // 2) attn_strength = pre_state @ W_aw^T + b_aw   (N=1024, K=512, splitK=8)
    gemm64_kernel<<<dim3(D2H/128, 8), 256>>>(pre_state, H_, W_aw, nullptr, nullptr, 0, D2H, H_, 8);
    splitk_reduce<<<(B_*D2H + 255)/256, 256>>>(b_aw, attn_strength, D2H, D2H, 8);

    // 3) attn scores + softmax
    attn_score_kernel<<<dim3(B_, 8), 256>>>(enc);
    softmax256<<<B_, S_>>>();

    // 4) context (-> g_x1[:,0:1024]) + select_reading (-> g_x[:,512:1536])
    ctxsel_kernel<<<dim3(B_, 4), 256>>>(enc, seq, input_idx, ppc);

    // 5) attn_reading = x1 @ W_ac^T + b_ac -> g_x[:,0:512]  (N=512, K=1280, splitK=8)
    gemm64_kernel<<<dim3(H_/128, 8), 256>>>(x1, X1W, W_ac, nullptr, nullptr, 0, H_, X1W, 8);
    splitk_reduce<<<(B_*H_ + 255)/256, 256>>>(b_ac, x, XW, H_, 8);

    // 6) gi = x @ W_ih^T + b_ih  (N=1536, K=1536, splitK=8)
    gemm64_kernel<<<dim3(XW/128, 8), 256>>>(x, XW, W_ih, nullptr, nullptr, 0, XW, XW, 8);
    splitk_reduce<<<(B_*XW + 255)/256, 256>>>(b_ih, gi, XW, XW, 8);

    // 7) gh = pre_state @ W_hh^T + b_hh  (N=1536, K=512, splitK=8)
    gemm64_kernel<<<dim3(XW/128, 8), 256>>>(pre_state, H_, W_hh, nullptr, nullptr, 0, XW, H_, 8);
    splitk_reduce<<<(B_*XW + 255)/256, 256>>>(b_hh, gh, XW, XW, 8);

    // 8) GRU -> g_state and state output region
    gru_kernel<<<B_, H_>>>(pre_state, out + (size_t)B_ * ML_);

    // 9) score_g = state @ W_o^T + b_o -> logits[:, :32000]  (N=32000, K=512, direct)
    gemm64_kernel<<<dim3(V_/128, 1), 256>>>(state, H_, W_o, b_o, logits, ML_, V_, H_, 1);

    // 10) score_c fused (tanh(enc@W_c^T + b_c) . state) -> partials -> logits[:, 32000:]
    score_c_kernel<<<dim3(S_/64, H_/128, B_), 256>>>(enc, W_c, b_c, state);
    scred_kernel<<<B_, 256>>>();

    // 11) softmax over 32256
    softmax_big<<<B_, 1024>>>();

    // 12) out = [prob_g | 0] then scatter prob_c; also write prob_c output
    outbase_kernel<<<(B_*ML_)/256, 256>>>(out);
    probc_kernel<<<B_, S_>>>(seq, out);
}

// round 2
// speedup vs baseline: 1.4314x; 1.4314x over previous
#include <cuda_runtime.h>
#include <cstddef>

// Problem constants
#define B_   64
#define S_   256
#define H_   512
#define E_   256
#define V_   32000
#define ML_  32256
#define D2H  1024          // 2*H
#define XW   1536          // 3*H (width of x, gi, gh)
#define X1W  1280          // 2*H + E

// packed fp32x2 FMA (Blackwell): d = a*b + c, elementwise on 2-lane fp32 pairs
#define FMA2(c, a, b) asm("fma.rn.f32x2 %0, %1, %2, %3;" \
    : "=l"(c) : "l"(a), "l"(b), "l"(c))

// ---------------- scratch (device globals; no allocation allowed) ----------------
__device__ float g_attn_strength[B_ * D2H];
__device__ float g_scores[B_ * S_];          // attn scores -> weights (in place)
__device__ float g_x1[B_ * X1W];             // [context | embedding]
__device__ float g_x [B_ * XW];              // [attn_reading | select_reading]
__device__ float g_gi[B_ * XW];
__device__ float g_gh[B_ * XW];
__device__ float g_state[B_ * H_];
__device__ float g_logits[B_ * ML_];         // [score_g | score_c] -> probs (in place)
__device__ float g_part[2 * B_ * V_];        // split-K partials (largest: score_g k=2)
__device__ float g_scpart[4 * B_ * S_];      // score_c N-tile partials

// ---------------- generic fp32 GEMM: C[64,N] = A[64,K] @ B[N,K]^T (+bias) --------
// BM=64, BN=128, BK=16, 256 threads, 4x8 microtile per thread, FFMA2 inner loop.
// kSplit>1: writes per-split partials to g_part (reduced later, fixed order).
__global__ void __launch_bounds__(256) gemm64_kernel(
    const float* __restrict__ A, int lda,
    const float* __restrict__ Bm,
    const float* __restrict__ bias,
    float* __restrict__ C, int ldc,
    int N, int K, int kSplit)
{
    __shared__ __align__(16) float2 As2[16][64];   // A values duplicated (v,v)
    __shared__ __align__(16) float  Bs[16][128];
    const int tid  = threadIdx.x;
    const int tx   = tid & 15;
    const int ty   = tid >> 4;
    const int arow = tid >> 2;           // 0..63
    const int akv  = (tid & 3) * 4;      // 0,4,8,12
    const int n0   = blockIdx.x * 128;
    const int kLen = K / kSplit;
    const int k0   = blockIdx.y * kLen;

    const float* Ag  = A  + (size_t)arow * lda + k0 + akv;
    const float* Bg0 = Bm + (size_t)(n0 + arow) * K + k0 + akv;
    const float* Bg1 = Bm + (size_t)(n0 + 64 + arow) * K + k0 + akv;

    unsigned long long acc[4][4];        // 4 rows x 4 col-pairs, packed fp32x2
    #pragma unroll
    for (int i = 0; i < 4; i++)
        #pragma unroll
        for (int p = 0; p < 4; p++) acc[i][p] = 0ull;

    for (int kb = 0; kb < kLen; kb += 16) {
        float4 av  = *(const float4*)(Ag  + kb);
        float4 bv0 = *(const float4*)(Bg0 + kb);
        float4 bv1 = *(const float4*)(Bg1 + kb);
        __syncthreads();
        As2[akv+0][arow] = make_float2(av.x, av.x);
        As2[akv+1][arow] = make_float2(av.y, av.y);
        As2[akv+2][arow] = make_float2(av.z, av.z);
        As2[akv+3][arow] = make_float2(av.w, av.w);
        Bs[akv+0][arow] = bv0.x; Bs[akv+1][arow] = bv0.y;
        Bs[akv+2][arow] = bv0.z; Bs[akv+3][arow] = bv0.w;
        Bs[akv+0][64+arow] = bv1.x; Bs[akv+1][64+arow] = bv1.y;
        Bs[akv+2][64+arow] = bv1.z; Bs[akv+3][64+arow] = bv1.w;
        __syncthreads();
        #pragma unroll
        for (int k = 0; k < 16; k++) {
            ulonglong2 a01 = *(const ulonglong2*)&As2[k][ty*4];
            ulonglong2 a23 = *(const ulonglong2*)&As2[k][ty*4+2];
            ulonglong2 b01 = *(const ulonglong2*)&Bs[k][tx*8];
            ulonglong2 b23 = *(const ulonglong2*)&Bs[k][tx*8+4];
            unsigned long long ar[4] = {a01.x, a01.y, a23.x, a23.y};
            unsigned long long br[4] = {b01.x, b01.y, b23.x, b23.y};
            #pragma unroll
            for (int i = 0; i < 4; i++)
                #pragma unroll
                for (int p = 0; p < 4; p++)
                    FMA2(acc[i][p], ar[i], br[p]);
        }
    }

    if (kSplit == 1) {
        #pragma unroll
        for (int i = 0; i < 4; i++) {
            int r = ty*4 + i;
            #pragma unroll
            for (int p = 0; p < 4; p++) {
                int c = n0 + tx*8 + p*2;
                float lo = __uint_as_float((unsigned)acc[i][p]);
                float hi = __uint_as_float((unsigned)(acc[i][p] >> 32));
                if (bias) { lo += bias[c]; hi += bias[c+1]; }
                C[(size_t)r * ldc + c]     = lo;
                C[(size_t)r * ldc + c + 1] = hi;
            }
        }
    } else {
        float* P = g_part + (size_t)blockIdx.y * 64 * N;
        #pragma unroll
        for (int i = 0; i < 4; i++) {
            int r = ty*4 + i;
            #pragma unroll
            for (int p = 0; p < 4; p++) {
                int c = n0 + tx*8 + p*2;
                P[(size_t)r * N + c]     = __uint_as_float((unsigned)acc[i][p]);
                P[(size_t)r * N + c + 1] = __uint_as_float((unsigned)(acc[i][p] >> 32));
            }
        }
    }
}

// Fixed-order (deterministic) split-K reduction: C = bias + sum_z part[z]
__global__ void splitk_reduce(const float* __restrict__ bias,
                              float* __restrict__ C, int ldc, int N, int kSplit)
{
    int idx = blockIdx.x * blockDim.x + threadIdx.x;
    int total = 64 * N;
    if (idx >= total) return;
    int m = idx / N, n = idx - m * N;
    float s = bias ? bias[n] : 0.f;
    for (int z = 0; z < kSplit; z++) s += g_part[(size_t)z * total + idx];
    C[(size_t)m * ldc + n] = s;
}

// ---------------- score_c fused kernel -------------------------------------------
// For batch b, s-tile (64 rows), h-tile (128 cols):
//   F = enc_tile @ W_c^T ; partial[s] = sum_h tanh(F + b_c[h]) * state[b,h]
// Writes per-h-tile partials to g_scpart (reduced in fixed order by scred_kernel).
__global__ void __launch_bounds__(256) score_c_kernel(
    const float* __restrict__ enc,
    const float* __restrict__ W_c,
    const float* __restrict__ b_c,
    const float* __restrict__ state)
{
    __shared__ __align__(16) float2 As2[16][64];
    __shared__ __align__(16) float  Bs[16][128];
    __shared__ float red[64][17];
    const int tid  = threadIdx.x;
    const int tx   = tid & 15;
    const int ty   = tid >> 4;
    const int arow = tid >> 2;
    const int akv  = (tid & 3) * 4;
    const int s0   = blockIdx.x * 64;       // 0..3
    const int n0   = blockIdx.y * 128;      // 0..3
    const int b    = blockIdx.z;
    const int K    = D2H;                   // 1024

    const float* A   = enc + ((size_t)b * S_ + s0) * K;
    const float* Ag  = A   + (size_t)arow * K + akv;
    const float* Bg0 = W_c + (size_t)(n0 + arow) * K + akv;
    const float* Bg1 = W_c + (size_t)(n0 + 64 + arow) * K + akv;

    unsigned long long acc[4][4];
    #pragma unroll
    for (int i = 0; i < 4; i++)
        #pragma unroll
        for (int p = 0; p < 4; p++) acc[i][p] = 0ull;

    for (int kb = 0; kb < K; kb += 16) {
        float4 av  = *(const float4*)(Ag  + kb);
        float4 bv0 = *(const float4*)(Bg0 + kb);
        float4 bv1 = *(const float4*)(Bg1 + kb);
        __syncthreads();
        As2[akv+0][arow] = make_float2(av.x, av.x);
        As2[akv+1][arow] = make_float2(av.y, av.y);
        As2[akv+2][arow] = make_float2(av.z, av.z);
        As2[akv+3][arow] = make_float2(av.w, av.w);
        Bs[akv+0][arow] = bv0.x; Bs[akv+1][arow] = bv0.y;
        Bs[akv+2][arow] = bv0.z; Bs[akv+3][arow] = bv0.w;
        Bs[akv+0][64+arow] = bv1.x; Bs[akv+1][64+arow] = bv1.y;
        Bs[akv+2][64+arow] = bv1.z; Bs[akv+3][64+arow] = bv1.w;
        __syncthreads();
        #pragma unroll
        for (int k = 0; k < 16; k++) {
            ulonglong2 a01 = *(const ulonglong2*)&As2[k][ty*4];
            ulonglong2 a23 = *(const ulonglong2*)&As2[k][ty*4+2];
            ulonglong2 b01 = *(const ulonglong2*)&Bs[k][tx*8];
            ulonglong2 b23 = *(const ulonglong2*)&Bs[k][tx*8+4];
            unsigned long long ar[4] = {a01.x, a01.y, a23.x, a23.y};
            unsigned long long br[4] = {b01.x, b01.y, b23.x, b23.y};
            #pragma unroll
            for (int i = 0; i < 4; i++)
                #pragma unroll
                for (int p = 0; p < 4; p++)
                    FMA2(acc[i][p], ar[i], br[p]);
        }
    }

    // epilogue: tanh + weighted reduction over h
    float st[8], bc[8];
    #pragma unroll
    for (int j = 0; j < 8; j++) {
        int c = n0 + tx*8 + j;
        st[j] = state[(size_t)b * H_ + c];
        bc[j] = b_c[c];
    }
    float part[4];
    #pragma unroll
    for (int i = 0; i < 4; i++) {
        float p = 0.f;
        #pragma unroll
        for (int q = 0; q < 4; q++) {
            float lo = __uint_as_float((unsigned)acc[i][q]);
            float hi = __uint_as_float((unsigned)(acc[i][q] >> 32));
            p += tanhf(lo + bc[q*2])   * st[q*2];
            p += tanhf(hi + bc[q*2+1]) * st[q*2+1];
        }
        part[i] = p;
    }
    __syncthreads();
    #pragma unroll
    for (int i = 0; i < 4; i++) red[ty*4 + i][tx] = part[i];
    __syncthreads();
    if (tid < 64) {
        float s = 0.f;
        #pragma unroll
        for (int x = 0; x < 16; x++) s += red[tid][x];
        g_scpart[(size_t)blockIdx.y * (B_ * S_) + b * S_ + s0 + tid] = s;
    }
}

__global__ void scred_kernel()
{
    int idx = blockIdx.x * 256 + threadIdx.x;   // 64*256
    int b = idx >> 8, s = idx & 255;
    float v = g_scpart[idx] + g_scpart[B_*S_ + idx]
            + g_scpart[2*B_*S_ + idx] + g_scpart[3*B_*S_ + idx];
    g_logits[(size_t)b * ML_ + V_ + s] = v;
}

// ---------------- attention scores: scores[b,s] = enc[b,s,:] . strength[b,:] -----
__global__ void __launch_bounds__(256) attn_score_kernel(const float* __restrict__ enc)
{
    __shared__ float sm[D2H];
    const int b = blockIdx.x, t = threadIdx.x;
    for (int d = t; d < D2H; d += 256) sm[d] = g_attn_strength[b * D2H + d];
    __syncthreads();
    const int warp = t >> 5, lane = t & 31;
    #pragma unroll
    for (int r = 0; r < 4; r++) {
        int s = blockIdx.y * 32 + warp + r * 8;
        const float4* row = (const float4*)(enc + ((size_t)b * S_ + s) * D2H);
        float sum = 0.f;
        for (int q = lane; q < D2H/4; q += 32) {
            float4 v = row[q];
            sum += v.x*sm[q*4] + v.y*sm[q*4+1] + v.z*sm[q*4+2] + v.w*sm[q*4+3];
        }
        #pragma unroll
        for (int o = 16; o; o >>= 1) sum += __shfl_down_sync(0xffffffffu, sum, o);
        if (lane == 0) g_scores[b * S_ + s] = sum;
    }
}

__global__ void softmax256()
{
    int b = blockIdx.x, t = threadIdx.x;
    __shared__ float sm[256];
    float v = g_scores[b * S_ + t];
    sm[t] = v; __syncthreads();
    for (int o = 128; o; o >>= 1) { if (t < o) sm[t] = fmaxf(sm[t], sm[t+o]); __syncthreads(); }
    float m = sm[0]; __syncthreads();
    float e = expf(v - m);
    sm[t] = e; __syncthreads();
    for (int o = 128; o; o >>= 1) { if (t < o) sm[t] += sm[t+o]; __syncthreads(); }
    g_scores[b * S_ + t] = e / sm[0];
}

// ---------------- context + select_reading (one pass over enc) -------------------
__global__ void __launch_bounds__(256) ctxsel_kernel(
    const float* __restrict__ enc, const int* __restrict__ seq,
    const int* __restrict__ input_idx, const float* __restrict__ ppc)
{
    const int b = blockIdx.x;
    const int t = threadIdx.x;
    const int d = blockIdx.y * 256 + t;
    __shared__ float w[S_], sw[S_];
    int idxb = input_idx[b];
    w[t]  = g_scores[b * S_ + t];
    sw[t] = (seq[b * S_ + t] == idxb) ? ppc[b * S_ + t] : 0.f;
    __syncthreads();
    const float* e = enc + (size_t)b * S_ * D2H + d;
    float ctx = 0.f, sel = 0.f;
    #pragma unroll 4
    for (int s = 0; s < S_; s++) {
        float v = e[(size_t)s * D2H];
        ctx = fmaf(w[s], v, ctx);
        sel = fmaf(sw[s], v, sel);
    }
    g_x1[b * X1W + d]      = ctx;
    g_x [b * XW + H_ + d]  = sel;    // select_reading goes to cols [512,1536)
}

__global__ void embed_kernel(const int* __restrict__ input_idx,
                             const float* __restrict__ table)
{
    int b = blockIdx.x, t = threadIdx.x;
    int idx = input_idx[b];
    if (idx >= V_) idx = 2;
    g_x1[b * X1W + D2H + t] = table[(size_t)idx * E_ + t];
}

// ---------------- GRU cell --------------------------------------------------------
__global__ void gru_kernel(const float* __restrict__ pre_state, float* __restrict__ out_state)
{
    int b = blockIdx.x, h = threadIdx.x;   // 512 threads
    float ir = g_gi[b*XW + h],        hr = g_gh[b*XW + h];
    float iz = g_gi[b*XW + H_ + h],   hz = g_gh[b*XW + H_ + h];
    float in_= g_gi[b*XW + 2*H_ + h], hn = g_gh[b*XW + 2*H_ + h];
    float r = 1.f / (1.f + expf(-(ir + hr)));
    float z = 1.f / (1.f + expf(-(iz + hz)));
    float n = tanhf(in_ + r * hn);
    float ps = pre_state[b * H_ + h];
    float st = (1.f - z) * n + z * ps;
    g_state[b * H_ + h] = st;
    out_state[b * H_ + h] = st;
}

// ---------------- big softmax over 32256 ------------------------------------------
__global__ void __launch_bounds__(1024) softmax_big()
{
    int b = blockIdx.x, t = threadIdx.x;
    float* row = g_logits + (size_t)b * ML_;
    __shared__ float sred[32];
    float m = -1e30f;
    for (int i = t; i < ML_; i += 1024) m = fmaxf(m, row[i]);
    #pragma unroll
    for (int o = 16; o; o >>= 1) m = fmaxf(m, __shfl_xor_sync(0xffffffffu, m, o));
    if ((t & 31) == 0) sred[t >> 5] = m;
    __syncthreads();
    if (t < 32) {
        float x = sred[t];
        #pragma unroll
        for (int o = 16; o; o >>= 1) x = fmaxf(x, __shfl_xor_sync(0xffffffffu, x, o));
        sred[t] = x;
    }
    __syncthreads();
    m = sred[0];
    __syncthreads();
    float sum = 0.f;
    for (int i = t; i < ML_; i += 1024) {
        float e = expf(row[i] - m);
        row[i] = e;
        sum += e;
    }
    #pragma unroll
    for (int o = 16; o; o >>= 1) sum += __shfl_xor_sync(0xffffffffu, sum, o);
    if ((t & 31) == 0) sred[t >> 5] = sum;
    __syncthreads();
    if (t < 32) {
        float x = sred[t];
        #pragma unroll
        for (int o = 16; o; o >>= 1) x += __shfl_xor_sync(0xffffffffu, x, o);
        sred[t] = x;
    }
    __syncthreads();
    float inv = 1.f / sred[0];
    for (int i = t; i < ML_; i += 1024) row[i] *= inv;
}

// ---------------- final outputs ----------------------------------------------------
__global__ void outbase_kernel(float* __restrict__ out)
{
    int idx = blockIdx.x * 256 + threadIdx.x;   // 64*32256 total
    int v = idx % ML_;
    out[idx] = (v < V_) ? g_logits[idx] : 0.f;
}

__global__ void probc_kernel(const int* __restrict__ seq, float* __restrict__ out)
{
    int b = blockIdx.x, j = threadIdx.x;
    __shared__ int   sq[S_];
    __shared__ float pc[S_];
    sq[j] = seq[b * S_ + j];
    pc[j] = g_logits[(size_t)b * ML_ + V_ + j];
    __syncthreads();
    int tok = sq[j];
    float sum = 0.f;
    bool first = true;
    for (int i = 0; i < S_; i++) {
        bool mq = (sq[i] == tok);
        if (mq) sum += pc[i];
        if (mq && i < j) first = false;
    }
    // prob_c output (third output region)
    out[(size_t)B_ * ML_ + (size_t)B_ * H_ + b * S_ + j] = sum;
    // scatter: set on zero base, prob_g already added (unique writer per token per b)
    if (first) out[(size_t)b * ML_ + tok] += sum;
}

// ---------------- launch -----------------------------------------------------------
extern "C" void kernel_launch(void* const* d_in, const int* in_sizes, int n_in,
                              void* d_out, int out_size)
{
    const int*   input_idx = (const int*)  d_in[0];
    const float* enc       = (const float*)d_in[1];
    const int*   seq       = (const int*)  d_in[2];
    const float* pre_state = (const float*)d_in[3];
    const float* ppc       = (const float*)d_in[4];
    const float* table     = (const float*)d_in[5];
    const float* W_aw = (const float*)d_in[6];  const float* b_aw = (const float*)d_in[7];
    const float* W_ac = (const float*)d_in[8];  const float* b_ac = (const float*)d_in[9];
    const float* W_ih = (const float*)d_in[10]; const float* b_ih = (const float*)d_in[11];
    const float* W_hh = (const float*)d_in[12]; const float* b_hh = (const float*)d_in[13];
    const float* W_o  = (const float*)d_in[14]; const float* b_o  = (const float*)d_in[15];
    const float* W_c  = (const float*)d_in[16]; const float* b_c  = (const float*)d_in[17];
    float* out = (float*)d_out;

    float *attn_strength, *x1, *x, *gi, *gh, *state, *logits;
    cudaGetSymbolAddress((void**)&attn_strength, g_attn_strength);
    cudaGetSymbolAddress((void**)&x1, g_x1);
    cudaGetSymbolAddress((void**)&x,  g_x);
    cudaGetSymbolAddress((void**)&gi, g_gi);
    cudaGetSymbolAddress((void**)&gh, g_gh);
    cudaGetSymbolAddress((void**)&state,  g_state);
    cudaGetSymbolAddress((void**)&logits, g_logits);

    // 1) embedding gather -> g_x1[:,1024:1280]
    embed_kernel<<<B_, E_>>>(input_idx, table);

    // 2) attn_strength = pre_state @ W_aw^T + b_aw   (N=1024, K=512, splitK=8)
    gemm64_kernel<<<dim3(D2H/128, 8), 256>>>(pre_state, H_, W_aw, nullptr, nullptr, 0, D2H, H_, 8);
    splitk_reduce<<<(B_*D2H + 255)/256, 256>>>(b_aw, attn_strength, D2H, D2H, 8);

    // 3) attn scores + softmax
    attn_score_kernel<<<dim3(B_, 8), 256>>>(enc);
    softmax256<<<B_, S_>>>();

    // 4) context (-> g_x1[:,0:1024]) + select_reading (-> g_x[:,512:1536])
    ctxsel_kernel<<<dim3(B_, 4), 256>>>(enc, seq, input_idx, ppc);

    // 5) attn_reading = x1 @ W_ac^T + b_ac -> g_x[:,0:512]  (N=512, K=1280, splitK=8)
    gemm64_kernel<<<dim3(H_/128, 8), 256>>>(x1, X1W, W_ac, nullptr, nullptr, 0, H_, X1W, 8);
    splitk_reduce<<<(B_*H_ + 255)/256, 256>>>(b_ac, x, XW, H_, 8);

    // 6) gi = x @ W_ih^T + b_ih  (N=1536, K=1536, splitK=8)
    gemm64_kernel<<<dim3(XW/128, 8), 256>>>(x, XW, W_ih, nullptr, nullptr, 0, XW, XW, 8);
    splitk_reduce<<<(B_*XW + 255)/256, 256>>>(b_ih, gi, XW, XW, 8);

    // 7) gh = pre_state @ W_hh^T + b_hh  (N=1536, K=512, splitK=8)
    gemm64_kernel<<<dim3(XW/128, 8), 256>>>(pre_state, H_, W_hh, nullptr, nullptr, 0, XW, H_, 8);
    splitk_reduce<<<(B_*XW + 255)/256, 256>>>(b_hh, gh, XW, XW, 8);

    // 8) GRU -> g_state and state output region
    gru_kernel<<<B_, H_>>>(pre_state, out + (size_t)B_ * ML_);

    // 9) score_g = state @ W_o^T + b_o -> logits[:, :32000]  (N=32000, K=512, splitK=2)
    gemm64_kernel<<<dim3(V_/128, 2), 256>>>(state, H_, W_o, nullptr, nullptr, 0, V_, H_, 2);
    splitk_reduce<<<(B_*V_ + 255)/256, 256>>>(b_o, logits, ML_, V_, 2);

    // 10) score_c fused (tanh(enc@W_c^T + b_c) . state) -> partials -> logits[:, 32000:]
    score_c_kernel<<<dim3(S_/64, H_/128, B_), 256>>>(enc, W_c, b_c, state);
    scred_kernel<<<B_, 256>>>();

    // 11) softmax over 32256
    softmax_big<<<B_, 1024>>>();

    // 12) out = [prob_g | 0] then scatter prob_c; also write prob_c output
    outbase_kernel<<<(B_*ML_)/256, 256>>>(out);
    probc_kernel<<<B_, S_>>>(seq, out);
}

// round 3
// speedup vs baseline: 1.4669x; 1.0248x over previous
#include <cuda_runtime.h>
#include <cstddef>

// Problem constants
#define B_   64
#define S_   256
#define H_   512
#define E_   256
#define V_   32000
#define ML_  32256
#define D2H  1024          // 2*H
#define XW   1536          // 3*H (width of x, gi, gh)
#define X1W  1280          // 2*H + E

// packed fp32x2 FMA (Blackwell): d = a*b + c, elementwise on 2-lane fp32 pairs
#define FMA2(c, a, b) asm("fma.rn.f32x2 %0, %1, %2, %3;" \
    : "=l"(c) : "l"(a), "l"(b), "l"(c))

// ---------------- scratch (device globals; no allocation allowed) ----------------
__device__ float g_attn_strength[B_ * D2H];
__device__ float g_scores[B_ * S_];          // attn scores -> weights (in place)
__device__ float g_x1[B_ * X1W];             // [context | embedding]
__device__ float g_x [B_ * XW];              // [attn_reading | select_reading]
__device__ float g_gi[B_ * XW];
__device__ float g_gh[B_ * XW];
__device__ float g_state[B_ * H_];
__device__ float g_logits[B_ * ML_];         // [score_g | score_c] -> probs (in place)
__device__ float g_part[2 * B_ * V_];        // split-K partials (largest: score_g k=2)
__device__ float g_scpart[4 * B_ * S_];      // score_c N-tile partials

// ---------------- generic fp32 GEMM: C[64,N] = A[64,K] @ B[N,K]^T (+bias) --------
// BM=64, BN=128, BK=16, 256 threads, 4x8 microtile, FFMA2 inner loop,
// register-prefetch pipeline (next tile's global loads issued before compute).
__global__ void __launch_bounds__(256) gemm64_kernel(
    const float* __restrict__ A, int lda,
    const float* __restrict__ Bm,
    const float* __restrict__ bias,
    float* __restrict__ C, int ldc,
    int N, int K, int kSplit)
{
    __shared__ __align__(16) float2 As2[16][64];   // A values duplicated (v,v)
    __shared__ __align__(16) float  Bs[16][128];
    const int tid  = threadIdx.x;
    const int tx   = tid & 15;
    const int ty   = tid >> 4;
    const int arow = tid >> 2;           // 0..63
    const int akv  = (tid & 3) * 4;      // 0,4,8,12
    const int n0   = blockIdx.x * 128;
    const int kLen = K / kSplit;
    const int k0   = blockIdx.y * kLen;

    const float* Ag  = A  + (size_t)arow * lda + k0 + akv;
    const float* Bg0 = Bm + (size_t)(n0 + arow) * K + k0 + akv;
    const float* Bg1 = Bm + (size_t)(n0 + 64 + arow) * K + k0 + akv;

    unsigned long long acc[4][4];        // 4 rows x 4 col-pairs, packed fp32x2
    #pragma unroll
    for (int i = 0; i < 4; i++)
        #pragma unroll
        for (int p = 0; p < 4; p++) acc[i][p] = 0ull;

    // prologue: prefetch tile 0
    float4 av  = *(const float4*)(Ag);
    float4 bv0 = *(const float4*)(Bg0);
    float4 bv1 = *(const float4*)(Bg1);

    for (int kb = 0; kb < kLen; kb += 16) {
        __syncthreads();
        As2[akv+0][arow] = make_float2(av.x, av.x);
        As2[akv+1][arow] = make_float2(av.y, av.y);
        As2[akv+2][arow] = make_float2(av.z, av.z);
        As2[akv+3][arow] = make_float2(av.w, av.w);
        Bs[akv+0][arow] = bv0.x; Bs[akv+1][arow] = bv0.y;
        Bs[akv+2][arow] = bv0.z; Bs[akv+3][arow] = bv0.w;
        Bs[akv+0][64+arow] = bv1.x; Bs[akv+1][64+arow] = bv1.y;
        Bs[akv+2][64+arow] = bv1.z; Bs[akv+3][64+arow] = bv1.w;
        __syncthreads();
        // prefetch next tile (overlaps with compute below)
        if (kb + 16 < kLen) {
            av  = *(const float4*)(Ag  + kb + 16);
            bv0 = *(const float4*)(Bg0 + kb + 16);
            bv1 = *(const float4*)(Bg1 + kb + 16);
        }
        #pragma unroll
        for (int k = 0; k < 16; k++) {
            ulonglong2 a01 = *(const ulonglong2*)&As2[k][ty*4];
            ulonglong2 a23 = *(const ulonglong2*)&As2[k][ty*4+2];
            ulonglong2 b01 = *(const ulonglong2*)&Bs[k][tx*8];
            ulonglong2 b23 = *(const ulonglong2*)&Bs[k][tx*8+4];
            unsigned long long ar[4] = {a01.x, a01.y, a23.x, a23.y};
            unsigned long long br[4] = {b01.x, b01.y, b23.x, b23.y};
            #pragma unroll
            for (int i = 0; i < 4; i++)
                #pragma unroll
                for (int p = 0; p < 4; p++)
                    FMA2(acc[i][p], ar[i], br[p]);
        }
    }

    if (kSplit == 1) {
        #pragma unroll
        for (int i = 0; i < 4; i++) {
            int r = ty*4 + i;
            #pragma unroll
            for (int p = 0; p < 4; p++) {
                int c = n0 + tx*8 + p*2;
                float lo = __uint_as_float((unsigned)acc[i][p]);
                float hi = __uint_as_float((unsigned)(acc[i][p] >> 32));
                if (bias) { lo += bias[c]; hi += bias[c+1]; }
                C[(size_t)r * ldc + c]     = lo;
                C[(size_t)r * ldc + c + 1] = hi;
            }
        }
    } else {
        float* P = g_part + (size_t)blockIdx.y * 64 * N;
        #pragma unroll
        for (int i = 0; i < 4; i++) {
            int r = ty*4 + i;
            #pragma unroll
            for (int p = 0; p < 4; p++) {
                int c = n0 + tx*8 + p*2;
                P[(size_t)r * N + c]     = __uint_as_float((unsigned)acc[i][p]);
                P[(size_t)r * N + c + 1] = __uint_as_float((unsigned)(acc[i][p] >> 32));
            }
        }
    }
}

// Fixed-order (deterministic) split-K reduction: C = bias + sum_z part[z]
__global__ void splitk_reduce(const float* __restrict__ bias,
                              float* __restrict__ C, int ldc, int N, int kSplit)
{
    int idx = blockIdx.x * blockDim.x + threadIdx.x;
    int total = 64 * N;
    if (idx >= total) return;
    int m = idx / N, n = idx - m * N;
    float s = bias ? bias[n] : 0.f;
    for (int z = 0; z < kSplit; z++) s += g_part[(size_t)z * total + idx];
    C[(size_t)m * ldc + n] = s;
}

// ---------------- score_c fused kernel -------------------------------------------
// For batch b, s-tile (64 rows), h-tile (128 cols):
//   F = enc_tile @ W_c^T ; partial[s] = sum_h tanh(F + b_c[h]) * state[b,h]
// Writes per-h-tile partials to g_scpart (reduced in fixed order by scred_kernel).
__global__ void __launch_bounds__(256) score_c_kernel(
    const float* __restrict__ enc,
    const float* __restrict__ W_c,
    const float* __restrict__ b_c,
    const float* __restrict__ state)
{
    __shared__ __align__(16) float2 As2[16][64];
    __shared__ __align__(16) float  Bs[16][128];
    __shared__ float red[64][17];
    const int tid  = threadIdx.x;
    const int tx   = tid & 15;
    const int ty   = tid >> 4;
    const int arow = tid >> 2;
    const int akv  = (tid & 3) * 4;
    const int s0   = blockIdx.x * 64;       // 0..3
    const int n0   = blockIdx.y * 128;      // 0..3
    const int b    = blockIdx.z;
    const int K    = D2H;                   // 1024

    const float* A   = enc + ((size_t)b * S_ + s0) * K;
    const float* Ag  = A   + (size_t)arow * K + akv;
    const float* Bg0 = W_c + (size_t)(n0 + arow) * K + akv;
    const float* Bg1 = W_c + (size_t)(n0 + 64 + arow) * K + akv;

    unsigned long long acc[4][4];
    #pragma unroll
    for (int i = 0; i < 4; i++)
        #pragma unroll
        for (int p = 0; p < 4; p++) acc[i][p] = 0ull;

    float4 av  = *(const float4*)(Ag);
    float4 bv0 = *(const float4*)(Bg0);
    float4 bv1 = *(const float4*)(Bg1);

    for (int kb = 0; kb < K; kb += 16) {
        __syncthreads();
        As2[akv+0][arow] = make_float2(av.x, av.x);
        As2[akv+1][arow] = make_float2(av.y, av.y);
        As2[akv+2][arow] = make_float2(av.z, av.z);
        As2[akv+3][arow] = make_float2(av.w, av.w);
        Bs[akv+0][arow] = bv0.x; Bs[akv+1][arow] = bv0.y;
        Bs[akv+2][arow] = bv0.z; Bs[akv+3][arow] = bv0.w;
        Bs[akv+0][64+arow] = bv1.x; Bs[akv+1][64+arow] = bv1.y;
        Bs[akv+2][64+arow] = bv1.z; Bs[akv+3][64+arow] = bv1.w;
        __syncthreads();
        if (kb + 16 < K) {
            av  = *(const float4*)(Ag  + kb + 16);
            bv0 = *(const float4*)(Bg0 + kb + 16);
            bv1 = *(const float4*)(Bg1 + kb + 16);
        }
        #pragma unroll
        for (int k = 0; k < 16; k++) {
            ulonglong2 a01 = *(const ulonglong2*)&As2[k][ty*4];
            ulonglong2 a23 = *(const ulonglong2*)&As2[k][ty*4+2];
            ulonglong2 b01 = *(const ulonglong2*)&Bs[k][tx*8];
            ulonglong2 b23 = *(const ulonglong2*)&Bs[k][tx*8+4];
            unsigned long long ar[4] = {a01.x, a01.y, a23.x, a23.y};
            unsigned long long br[4] = {b01.x, b01.y, b23.x, b23.y};
            #pragma unroll
            for (int i = 0; i < 4; i++)
                #pragma unroll
                for (int p = 0; p < 4; p++)
                    FMA2(acc[i][p], ar[i], br[p]);
        }
    }

    // epilogue: tanh + weighted reduction over h
    float st[8], bc[8];
    #pragma unroll
    for (int j = 0; j < 8; j++) {
        int c = n0 + tx*8 + j;
        st[j] = state[(size_t)b * H_ + c];
        bc[j] = b_c[c];
    }
    float part[4];
    #pragma unroll
    for (int i = 0; i < 4; i++) {
        float p = 0.f;
        #pragma unroll
        for (int q = 0; q < 4; q++) {
            float lo = __uint_as_float((unsigned)acc[i][q]);
            float hi = __uint_as_float((unsigned)(acc[i][q] >> 32));
            p += tanhf(lo + bc[q*2])   * st[q*2];
            p += tanhf(hi + bc[q*2+1]) * st[q*2+1];
        }
        part[i] = p;
    }
    __syncthreads();
    #pragma unroll
    for (int i = 0; i < 4; i++) red[ty*4 + i][tx] = part[i];
    __syncthreads();
    if (tid < 64) {
        float s = 0.f;
        #pragma unroll
        for (int x = 0; x < 16; x++) s += red[tid][x];
        g_scpart[(size_t)blockIdx.y * (B_ * S_) + b * S_ + s0 + tid] = s;
    }
}

__global__ void scred_kernel()
{
    int idx = blockIdx.x * 256 + threadIdx.x;   // 64*256
    int b = idx >> 8, s = idx & 255;
    float v = g_scpart[idx] + g_scpart[B_*S_ + idx]
            + g_scpart[2*B_*S_ + idx] + g_scpart[3*B_*S_ + idx];
    g_logits[(size_t)b * ML_ + V_ + s] = v;
}

// ---------------- attention scores: scores[b,s] = enc[b,s,:] . strength[b,:] -----
__global__ void __launch_bounds__(256) attn_score_kernel(const float* __restrict__ enc)
{
    __shared__ float sm[D2H];
    const int b = blockIdx.x, t = threadIdx.x;
    for (int d = t; d < D2H; d += 256) sm[d] = g_attn_strength[b * D2H + d];
    __syncthreads();
    const int warp = t >> 5, lane = t & 31;
    #pragma unroll
    for (int r = 0; r < 4; r++) {
        int s = blockIdx.y * 32 + warp + r * 8;
        const float4* row = (const float4*)(enc + ((size_t)b * S_ + s) * D2H);
        float sum = 0.f;
        for (int q = lane; q < D2H/4; q += 32) {
            float4 v = row[q];
            sum += v.x*sm[q*4] + v.y*sm[q*4+1] + v.z*sm[q*4+2] + v.w*sm[q*4+3];
        }
        #pragma unroll
        for (int o = 16; o; o >>= 1) sum += __shfl_down_sync(0xffffffffu, sum, o);
        if (lane == 0) g_scores[b * S_ + s] = sum;
    }
}

__global__ void softmax256()
{
    int b = blockIdx.x, t = threadIdx.x;
    __shared__ float sm[256];
    float v = g_scores[b * S_ + t];
    sm[t] = v; __syncthreads();
    for (int o = 128; o; o >>= 1) { if (t < o) sm[t] = fmaxf(sm[t], sm[t+o]); __syncthreads(); }
    float m = sm[0]; __syncthreads();
    float e = expf(v - m);
    sm[t] = e; __syncthreads();
    for (int o = 128; o; o >>= 1) { if (t < o) sm[t] += sm[t+o]; __syncthreads(); }
    g_scores[b * S_ + t] = e / sm[0];
}

// ---------------- context + select_reading (one pass over enc) -------------------
__global__ void __launch_bounds__(256) ctxsel_kernel(
    const float* __restrict__ enc, const int* __restrict__ seq,
    const int* __restrict__ input_idx, const float* __restrict__ ppc)
{
    const int b = blockIdx.x;
    const int t = threadIdx.x;
    const int d = blockIdx.y * 256 + t;
    __shared__ float w[S_], sw[S_];
    int idxb = input_idx[b];
    w[t]  = g_scores[b * S_ + t];
    sw[t] = (seq[b * S_ + t] == idxb) ? ppc[b * S_ + t] : 0.f;
    __syncthreads();
    const float* e = enc + (size_t)b * S_ * D2H + d;
    float ctx = 0.f, sel = 0.f;
    #pragma unroll 4
    for (int s = 0; s < S_; s++) {
        float v = e[(size_t)s * D2H];
        ctx = fmaf(w[s], v, ctx);
        sel = fmaf(sw[s], v, sel);
    }
    g_x1[b * X1W + d]      = ctx;
    g_x [b * XW + H_ + d]  = sel;    // select_reading goes to cols [512,1536)
}

__global__ void embed_kernel(const int* __restrict__ input_idx,
                             const float* __restrict__ table)
{
    int b = blockIdx.x, t = threadIdx.x;
    int idx = input_idx[b];
    if (idx >= V_) idx = 2;
    g_x1[b * X1W + D2H + t] = table[(size_t)idx * E_ + t];
}

// ---------------- GRU cell --------------------------------------------------------
__global__ void gru_kernel(const float* __restrict__ pre_state, float* __restrict__ out_state)
{
    int b = blockIdx.x, h = threadIdx.x;   // 512 threads
    float ir = g_gi[b*XW + h],        hr = g_gh[b*XW + h];
    float iz = g_gi[b*XW + H_ + h],   hz = g_gh[b*XW + H_ + h];
    float in_= g_gi[b*XW + 2*H_ + h], hn = g_gh[b*XW + 2*H_ + h];
    float r = 1.f / (1.f + expf(-(ir + hr)));
    float z = 1.f / (1.f + expf(-(iz + hz)));
    float n = tanhf(in_ + r * hn);
    float ps = pre_state[b * H_ + h];
    float st = (1.f - z) * n + z * ps;
    g_state[b * H_ + h] = st;
    out_state[b * H_ + h] = st;
}

// ---------------- big softmax over 32256, fused with final prob_g write -----------
// Writes: out[b, v] = prob_g (v < V_), 0 for v in [V_, ML_); keeps prob_c region
// (normalized) in g_logits for probc_kernel.
__global__ void __launch_bounds__(1024) softmax_big(float* __restrict__ out)
{
    int b = blockIdx.x, t = threadIdx.x;
    float* row = g_logits + (size_t)b * ML_;
    float* orow = out + (size_t)b * ML_;
    __shared__ float sred[32];
    float m = -1e30f;
    for (int i = t; i < ML_; i += 1024) m = fmaxf(m, row[i]);
    #pragma unroll
    for (int o = 16; o; o >>= 1) m = fmaxf(m, __shfl_xor_sync(0xffffffffu, m, o));
    if ((t & 31) == 0) sred[t >> 5] = m;
    __syncthreads();
    if (t < 32) {
        float x = sred[t];
        #pragma unroll
        for (int o = 16; o; o >>= 1) x = fmaxf(x, __shfl_xor_sync(0xffffffffu, x, o));
        sred[t] = x;
    }
    __syncthreads();
    m = sred[0];
    __syncthreads();
    float sum = 0.f;
    for (int i = t; i < ML_; i += 1024) {
        float e = expf(row[i] - m);
        row[i] = e;
        sum += e;
    }
    #pragma unroll
    for (int o = 16; o; o >>= 1) sum += __shfl_xor_sync(0xffffffffu, sum, o);
    if ((t & 31) == 0) sred[t >> 5] = sum;
    __syncthreads();
    if (t < 32) {
        float x = sred[t];
        #pragma unroll
        for (int o = 16; o; o >>= 1) x += __shfl_xor_sync(0xffffffffu, x, o);
        sred[t] = x;
    }
    __syncthreads();
    float inv = 1.f / sred[0];
    for (int i = t; i < ML_; i += 1024) {
        float v = row[i] * inv;
        if (i < V_) {
            orow[i] = v;                 // prob_g directly to output
        } else {
            orow[i] = 0.f;               // zero pad (probc scatters on top)
            row[i]  = v;                 // normalized prob_c0 for probc_kernel
        }
    }
}

__global__ void probc_kernel(const int* __restrict__ seq, float* __restrict__ out)
{
    int b = blockIdx.x, j = threadIdx.x;
    __shared__ int   sq[S_];
    __shared__ float pc[S_];
    sq[j] = seq[b * S_ + j];
    pc[j] = g_logits[(size_t)b * ML_ + V_ + j];
    __syncthreads();
    int tok = sq[j];
    float sum = 0.f;
    bool first = true;
    for (int i = 0; i < S_; i++) {
        bool mq = (sq[i] == tok);
        if (mq) sum += pc[i];
        if (mq && i < j) first = false;
    }
    // prob_c output (third output region)
    out[(size_t)B_ * ML_ + (size_t)B_ * H_ + b * S_ + j] = sum;
    // scatter: set on zero base, prob_g already added (unique writer per token per b)
    if (first) out[(size_t)b * ML_ + tok] += sum;
}

// ---------------- launch -----------------------------------------------------------
extern "C" void kernel_launch(void* const* d_in, const int* in_sizes, int n_in,
                              void* d_out, int out_size)
{
    const int*   input_idx = (const int*)  d_in[0];
    const float* enc       = (const float*)d_in[1];
    const int*   seq       = (const int*)  d_in[2];
    const float* pre_state = (const float*)d_in[3];
    const float* ppc       = (const float*)d_in[4];
    const float* table     = (const float*)d_in[5];
    const float* W_aw = (const float*)d_in[6];  const float* b_aw = (const float*)d_in[7];
    const float* W_ac = (const float*)d_in[8];  const float* b_ac = (const float*)d_in[9];
    const float* W_ih = (const float*)d_in[10]; const float* b_ih = (const float*)d_in[11];
    const float* W_hh = (const float*)d_in[12]; const float* b_hh = (const float*)d_in[13];
    const float* W_o  = (const float*)d_in[14]; const float* b_o  = (const float*)d_in[15];
    const float* W_c  = (const float*)d_in[16]; const float* b_c  = (const float*)d_in[17];
    float* out = (float*)d_out;

    float *attn_strength, *x1, *x, *gi, *gh, *state, *logits;
    cudaGetSymbolAddress((void**)&attn_strength, g_attn_strength);
    cudaGetSymbolAddress((void**)&x1, g_x1);
    cudaGetSymbolAddress((void**)&x,  g_x);
    cudaGetSymbolAddress((void**)&gi, g_gi);
    cudaGetSymbolAddress((void**)&gh, g_gh);
    cudaGetSymbolAddress((void**)&state,  g_state);
    cudaGetSymbolAddress((void**)&logits, g_logits);

    // 1) embedding gather -> g_x1[:,1024:1280]
    embed_kernel<<<B_, E_>>>(input_idx, table);

    // 2) attn_strength = pre_state @ W_aw^T + b_aw   (N=1024, K=512, splitK=8)
    gemm64_kernel<<<dim3(D2H/128, 8), 256>>>(pre_state, H_, W_aw, nullptr, nullptr, 0, D2H, H_, 8);
    splitk_reduce<<<(B_*D2H + 255)/256, 256>>>(b_aw, attn_strength, D2H, D2H, 8);

    // 3) attn scores + softmax
    attn_score_kernel<<<dim3(B_, 8), 256>>>(enc);
    softmax256<<<B_, S_>>>();

    // 4) context (-> g_x1[:,0:1024]) + select_reading (-> g_x[:,512:1536])
    ctxsel_kernel<<<dim3(B_, 4), 256>>>(enc, seq, input_idx, ppc);

    // 5) attn_reading = x1 @ W_ac^T + b_ac -> g_x[:,0:512]  (N=512, K=1280, splitK=8)
    gemm64_kernel<<<dim3(H_/128, 8), 256>>>(x1, X1W, W_ac, nullptr, nullptr, 0, H_, X1W, 8);
    splitk_reduce<<<(B_*H_ + 255)/256, 256>>>(b_ac, x, XW, H_, 8);

    // 6) gi = x @ W_ih^T + b_ih  (N=1536, K=1536, splitK=8)
    gemm64_kernel<<<dim3(XW/128, 8), 256>>>(x, XW, W_ih, nullptr, nullptr, 0, XW, XW, 8);
    splitk_reduce<<<(B_*XW + 255)/256, 256>>>(b_ih, gi, XW, XW, 8);

    // 7) gh = pre_state @ W_hh^T + b_hh  (N=1536, K=512, splitK=8)
    gemm64_kernel<<<dim3(XW/128, 8), 256>>>(pre_state, H_, W_hh, nullptr, nullptr, 0, XW, H_, 8);
    splitk_reduce<<<(B_*XW + 255)/256, 256>>>(b_hh, gh, XW, XW, 8);

    // 8) GRU -> g_state and state output region
    gru_kernel<<<B_, H_>>>(pre_state, out + (size_t)B_ * ML_);

    // 9) score_g = state @ W_o^T + b_o -> logits[:, :32000]  (N=32000, K=512, splitK=2)
    gemm64_kernel<<<dim3(V_/128, 2), 256>>>(state, H_, W_o, nullptr, nullptr, 0, V_, H_, 2);
    splitk_reduce<<<(B_*V_ + 255)/256, 256>>>(b_o, logits, ML_, V_, 2);

    // 10) score_c fused (tanh(enc@W_c^T + b_c) . state) -> partials -> logits[:, 32000:]
    score_c_kernel<<<dim3(S_/64, H_/128, B_), 256>>>(enc, W_c, b_c, state);
    scred_kernel<<<B_, 256>>>();

    // 11) softmax over 32256 (fused: writes prob_g + zero pad directly to out)
    softmax_big<<<B_, 1024>>>(out);

    // 12) scatter prob_c into out; also write prob_c output region
    probc_kernel<<<B_, S_>>>(seq, out);
}